// round 1
// baseline (speedup 1.0000x reference)
#include <cuda_runtime.h>
#include <math.h>

#define KP 16384
#define DP 2048
#define DECAYF 0.99f
#define THRESHF 0.5f

// __device__ scratch (no allocations allowed)
__device__ float g_dot[KP];     // z . p_i
__device__ float g_pn2[KP];     // ||p_i||^2
__device__ float g_logits[KP];  // first logits
__device__ float g_l2[KP];      // logits2
__device__ float g_a[KP];       // EMA coef of z
__device__ float g_b[KP];       // EMA coef of p
__device__ int   g_evict;
__device__ int   g_evict_idx;

// ---------------- kernel 1: per-row dot + norm ----------------
__global__ void k1_dots(const float* __restrict__ z, const float* __restrict__ p) {
    __shared__ float4 zs[DP / 4];
    for (int i = threadIdx.x; i < DP / 4; i += blockDim.x)
        zs[i] = ((const float4*)z)[i];
    __syncthreads();
    int warp = threadIdx.x >> 5, lane = threadIdx.x & 31;
    int row = (blockIdx.x << 3) + warp;  // 8 warps/block
    const float4* pr = (const float4*)(p + (size_t)row * DP);
    float dot = 0.f, n2 = 0.f;
    #pragma unroll
    for (int i = lane; i < DP / 4; i += 32) {
        float4 a = pr[i], b = zs[i];
        dot += a.x * b.x + a.y * b.y + a.z * b.z + a.w * b.w;
        n2  += a.x * a.x + a.y * a.y + a.z * a.z + a.w * a.w;
    }
    #pragma unroll
    for (int o = 16; o; o >>= 1) {
        dot += __shfl_down_sync(0xffffffffu, dot, o);
        n2  += __shfl_down_sync(0xffffffffu, n2, o);
    }
    if (lane == 0) { g_dot[row] = dot; g_pn2[row] = n2; }
}

// ---------------- block reduction helpers (blockDim = 1024) ----------------
__device__ __forceinline__ float block_sum(float v, float* red) {
    int lane = threadIdx.x & 31, w = threadIdx.x >> 5;
    #pragma unroll
    for (int o = 16; o; o >>= 1) v += __shfl_down_sync(0xffffffffu, v, o);
    if (lane == 0) red[w] = v;
    __syncthreads();
    if (w == 0) {
        v = red[lane];
        #pragma unroll
        for (int o = 16; o; o >>= 1) v += __shfl_down_sync(0xffffffffu, v, o);
        if (lane == 0) red[0] = v;
    }
    __syncthreads();
    float r = red[0];
    __syncthreads();
    return r;
}

__device__ __forceinline__ float block_max(float v, float* red) {
    int lane = threadIdx.x & 31, w = threadIdx.x >> 5;
    #pragma unroll
    for (int o = 16; o; o >>= 1) v = fmaxf(v, __shfl_down_sync(0xffffffffu, v, o));
    if (lane == 0) red[w] = v;
    __syncthreads();
    if (w == 0) {
        v = red[lane];
        #pragma unroll
        for (int o = 16; o; o >>= 1) v = fmaxf(v, __shfl_down_sync(0xffffffffu, v, o));
        if (lane == 0) red[0] = v;
    }
    __syncthreads();
    float r = red[0];
    __syncthreads();
    return r;
}

// argmax with first-occurrence (lowest index) tie-break
__device__ __forceinline__ void block_argmax(float v, int idx, float* red, int* redi,
                                             float* ov, int* oi) {
    int lane = threadIdx.x & 31, w = threadIdx.x >> 5;
    #pragma unroll
    for (int o = 16; o; o >>= 1) {
        float v2 = __shfl_down_sync(0xffffffffu, v, o);
        int   i2 = __shfl_down_sync(0xffffffffu, idx, o);
        if (v2 > v || (v2 == v && i2 < idx)) { v = v2; idx = i2; }
    }
    if (lane == 0) { red[w] = v; redi[w] = idx; }
    __syncthreads();
    if (w == 0) {
        v = red[lane]; idx = redi[lane];
        #pragma unroll
        for (int o = 16; o; o >>= 1) {
            float v2 = __shfl_down_sync(0xffffffffu, v, o);
            int   i2 = __shfl_down_sync(0xffffffffu, idx, o);
            if (v2 > v || (v2 == v && i2 < idx)) { v = v2; idx = i2; }
        }
        if (lane == 0) { red[0] = v; redi[0] = idx; }
    }
    __syncthreads();
    *ov = red[0]; *oi = redi[0];
    __syncthreads();
}

// argmin with first-occurrence tie-break
__device__ __forceinline__ void block_argmin(float v, int idx, float* red, int* redi,
                                             float* ov, int* oi) {
    int lane = threadIdx.x & 31, w = threadIdx.x >> 5;
    #pragma unroll
    for (int o = 16; o; o >>= 1) {
        float v2 = __shfl_down_sync(0xffffffffu, v, o);
        int   i2 = __shfl_down_sync(0xffffffffu, idx, o);
        if (v2 < v || (v2 == v && i2 < idx)) { v = v2; idx = i2; }
    }
    if (lane == 0) { red[w] = v; redi[w] = idx; }
    __syncthreads();
    if (w == 0) {
        v = red[lane]; idx = redi[lane];
        #pragma unroll
        for (int o = 16; o; o >>= 1) {
            float v2 = __shfl_down_sync(0xffffffffu, v, o);
            int   i2 = __shfl_down_sync(0xffffffffu, idx, o);
            if (v2 < v || (v2 == v && i2 < idx)) { v = v2; idx = i2; }
        }
        if (lane == 0) { red[0] = v; redi[0] = idx; }
    }
    __syncthreads();
    *ov = red[0]; *oi = redi[0];
    __syncthreads();
}

// ---------------- kernel 2: all scalars / reductions (one block, 1024 thr) ----------------
__global__ void k2_scalars(const float* __restrict__ z,
                           const float* __restrict__ usages,
                           const float* __restrict__ beta,
                           const float* __restrict__ gamma,
                           const float* __restrict__ temp,
                           float* __restrict__ out) {
    __shared__ float red[32];
    __shared__ int redi[32];
    const int tid = threadIdx.x;
    const float tempv = temp[0];
    float* out_us = out + 3 + (size_t)KP * DP;

    // ||z||^2
    float acc = 0.f;
    for (int i = tid; i < DP; i += 1024) { float v = z[i]; acc += v * v; }
    float znorm2 = block_sum(acc, red);
    float rz = rsqrtf(znorm2);

    // logits + max
    float mx = -INFINITY;
    for (int i = tid; i < KP; i += 1024) {
        float l = tempv * g_dot[i] * rz * rsqrtf(g_pn2[i]);
        g_logits[i] = l;
        mx = fmaxf(mx, l);
    }
    float maxl = block_max(mx, red);

    float x = (-maxl - beta[0]) / gamma[0];
    float u = 1.f / (1.f + expf(-x));
    int evict = (u >= THRESHF) ? 1 : 0;

    if (evict) {
        // argmin usages
        float mv = INFINITY; int mi = 0;
        for (int i = tid; i < KP; i += 1024) {
            float uv = usages[i];
            if (uv < mv) { mv = uv; mi = i; }
        }
        float bv; int bidx;
        block_argmin(mv, mi, red, redi, &bv, &bidx);

        for (int i = tid; i < KP; i += 1024) {
            float l2, nu;
            if (i == KP - 1) {
                l2 = tempv * znorm2 * rz * rz;  // temp * <zhat,zhat>
                nu = 1.0f;
            } else {
                int src = (i < bidx) ? i : i + 1;
                l2 = g_logits[src];
                nu = usages[src];
            }
            g_l2[i] = l2;
            out_us[i] = nu * DECAYF;
        }
        if (tid == 0) { g_evict = 1; g_evict_idx = bidx; }
    } else {
        float se = 0.f;
        for (int i = tid; i < KP; i += 1024) se += expf(g_logits[i] - maxl);
        float sumexp = block_sum(se, red);

        for (int i = tid; i < KP; i += 1024) {
            float y = expf(g_logits[i] - maxl) / sumexp;
            float delta = y * (1.f - u);
            float us = usages[i];
            float a = delta / (delta + us);
            float b = us / (us + delta);
            g_a[i] = a; g_b[i] = b;
            out_us[i] = (us + delta) * DECAYF;
            // analytic logits2: new_p = a*z + b*p
            float dotn = a * znorm2 + b * g_dot[i];
            float nn2 = a * a * znorm2 + 2.f * a * b * g_dot[i] + b * b * g_pn2[i];
            g_l2[i] = tempv * dotn * rz * rsqrtf(nn2);
        }
        if (tid == 0) { g_evict = 0; g_evict_idx = 0; }
    }
    __syncthreads();

    // argmax + logsumexp of logits2
    float mv2 = -INFINITY; int mi2 = 0;
    for (int i = tid; i < KP; i += 1024) {
        float l = g_l2[i];
        if (l > mv2) { mv2 = l; mi2 = i; }
    }
    float m2; int lab;
    block_argmax(mv2, mi2, red, redi, &m2, &lab);

    float s2 = 0.f;
    for (int i = tid; i < KP; i += 1024) s2 += expf(g_l2[i] - m2);
    float sum2 = block_sum(s2, red);

    if (tid == 0) {
        float l2lab = g_l2[lab];
        out[0] = logf(sum2) + m2 - l2lab;  // -log_softmax at label
        out[1] = (float)lab;
        out[2] = u;
    }
}

// ---------------- kernel 3: write new prototypes (128 MB) ----------------
// Reverse row order: tail of P is freshest in L2 after k1.
// Scalar f32 accesses because out+3 is only 4-byte aligned; still fully coalesced.
__global__ void k3_write(const float* __restrict__ z,
                         const float* __restrict__ p,
                         float* __restrict__ out) {
    int row = KP - 1 - blockIdx.x;
    float* orow = out + 3 + (size_t)row * DP;
    if (g_evict) {
        if (row == KP - 1) {
            for (int j = threadIdx.x; j < DP; j += blockDim.x) orow[j] = z[j];
        } else {
            int idx = g_evict_idx;
            const float* pr = p + (size_t)((row < idx) ? row : row + 1) * DP;
            for (int j = threadIdx.x; j < DP; j += blockDim.x) orow[j] = pr[j];
        }
    } else {
        float a = g_a[row], b = g_b[row];
        const float* pr = p + (size_t)row * DP;
        for (int j = threadIdx.x; j < DP; j += blockDim.x)
            orow[j] = fmaf(a, z[j], b * pr[j]);
    }
}

extern "C" void kernel_launch(void* const* d_in, const int* in_sizes, int n_in,
                              void* d_out, int out_size) {
    const float* z     = (const float*)d_in[0];
    const float* p     = (const float*)d_in[1];
    const float* us    = (const float*)d_in[2];
    const float* beta  = (const float*)d_in[3];
    const float* gamma = (const float*)d_in[4];
    const float* temp  = (const float*)d_in[5];
    float* out = (float*)d_out;

    k1_dots<<<KP / 8, 256>>>(z, p);
    k2_scalars<<<1, 1024>>>(z, us, beta, gamma, temp, out);
    k3_write<<<KP, 256>>>(z, p, out);
}